// round 14
// baseline (speedup 1.0000x reference)
#include <cuda_runtime.h>
#include <cuda_bf16.h>
#include <cstdint>
#include <math.h>

// Problem constants
#define BB   16
#define NN   128
#define DD   4424
#define D4   1106
#define D4P  1112
#define D2   2212
#define D2P  2216
#define NC   151
#define NP   51
#define MT   2048

// ---------------- scratch ------------------------------------------------------
__device__ __nv_bfloat16 g_featb[MT * DD];
__device__ __nv_bfloat16 g_compb[MT * D4P];
__device__ float         g_u1   [MT * D4];
__device__ __nv_bfloat16 g_oflb [MT * D2P];
__device__ __nv_bfloat16 g_umb  [MT * D4P];
__device__ __nv_bfloat16 g_WcT  [(size_t)D4 * DD];
__device__ __nv_bfloat16 g_WuT  [(size_t)D4 * D4P];
__device__ __nv_bfloat16 g_WoT  [(size_t)D4 * D2P];
__device__ __nv_bfloat16 g_WdT  [(size_t)DD * D4P];
__device__ float g_sim  [BB * NN * NN];
__device__ int   g_idx  [BB * NN * 2];
__device__ int   g_preds[MT];
__device__ float g_h1   [BB * 10 * NN * NN];
__device__ float g_adj  [BB * NN * NN];

// ---------------- PTX helpers --------------------------------------------------
__device__ __forceinline__ uint32_t smem_u32(const void* p) {
    uint32_t a;
    asm("{ .reg .u64 t; cvta.to.shared.u64 t, %1; cvt.u32.u64 %0, t; }" : "=r"(a) : "l"(p));
    return a;
}
__device__ __forceinline__ void cp16(uint32_t dst, const void* src, bool valid) {
    int sz = valid ? 16 : 0;
    asm volatile("cp.async.cg.shared.global [%0], [%1], 16, %2;"
                 :: "r"(dst), "l"(src), "r"(sz));
}
__device__ __forceinline__ void cp_commit() {
    asm volatile("cp.async.commit_group;" ::: "memory");
}
__device__ __forceinline__ void cp_wait0() {
    asm volatile("cp.async.wait_group 0;" ::: "memory");
}
__device__ __forceinline__ void cp_wait1() {
    asm volatile("cp.async.wait_group 1;" ::: "memory");
}
__device__ __forceinline__ void ldm_x4(uint32_t* r, uint32_t addr) {
    asm volatile("ldmatrix.sync.aligned.m8n8.x4.shared.b16 {%0,%1,%2,%3}, [%4];"
                 : "=r"(r[0]), "=r"(r[1]), "=r"(r[2]), "=r"(r[3]) : "r"(addr));
}
__device__ __forceinline__ void mma_bf16(float* c, const uint32_t* a,
                                         uint32_t b0, uint32_t b1) {
    asm volatile(
        "mma.sync.aligned.m16n8k16.row.col.f32.bf16.bf16.f32 "
        "{%0,%1,%2,%3}, {%4,%5,%6,%7}, {%8,%9}, {%0,%1,%2,%3};"
        : "+f"(c[0]), "+f"(c[1]), "+f"(c[2]), "+f"(c[3])
        : "r"(a[0]), "r"(a[1]), "r"(a[2]), "r"(a[3]), "r"(b0), "r"(b1));
}

#define GLDS 40

// ---------------- hgemm BN=64 (proven config) ----------------------------------
__global__ __launch_bounds__(256)
void hgemm(const __nv_bfloat16* __restrict__ A, int lda,
           const __nv_bfloat16* __restrict__ Bt, int ldb,
           const float* __restrict__ Res, int ldr,
           float* __restrict__ C, int ldc,
           __nv_bfloat16* __restrict__ Cb, int ldcb,
           int M, int N, int K, int doRelu, int doRes)
{
    __shared__ __nv_bfloat16 sA[2][128 * GLDS];
    __shared__ __nv_bfloat16 sB[2][64 * GLDS];

    int tid = threadIdx.x, lane = tid & 31, wid = tid >> 5;
    int wm_ = wid & 3;
    int wn_ = wid >> 2;
    int row0 = blockIdx.y * 128, col0 = blockIdx.x * 64;
    int nch = (K + 31) / 32;

    float acc[2][4][4];
#pragma unroll
    for (int i = 0; i < 2; i++)
#pragma unroll
        for (int j = 0; j < 4; j++)
#pragma unroll
            for (int q = 0; q < 4; q++) acc[i][j][q] = 0.f;

    uint32_t sa0 = smem_u32(&sA[0][0]);
    uint32_t sb0 = smem_u32(&sB[0][0]);

    int larow = tid >> 1;
    int laseg = (tid & 1) * 2;
    int lbrow = tid >> 2;
    int lbseg = tid & 3;

    {
        const __nv_bfloat16* ap = A + (size_t)(row0 + larow) * lda;
        const __nv_bfloat16* bp = Bt + (size_t)(col0 + lbrow) * ldb;
        bool brow = (col0 + lbrow) < N;
#pragma unroll
        for (int q = 0; q < 2; q++) {
            int k = (laseg + q) * 8;
            cp16(sa0 + (uint32_t)(larow * GLDS + k) * 2, ap + k, k + 8 <= K);
        }
        {
            int k = lbseg * 8;
            cp16(sb0 + (uint32_t)(lbrow * GLDS + k) * 2, bp + k, brow && (k + 8 <= K));
        }
    }
    cp_commit();

    for (int ch = 0; ch < nch; ch++) {
        if (ch + 1 < nch) {
            int s = (ch + 1) & 1;
            int k0 = (ch + 1) * 32;
            const __nv_bfloat16* ap = A + (size_t)(row0 + larow) * lda + k0;
            const __nv_bfloat16* bp = Bt + (size_t)(col0 + lbrow) * ldb + k0;
            bool brow = (col0 + lbrow) < N;
            uint32_t sa = sa0 + s * 128 * GLDS * 2;
            uint32_t sb = sb0 + s * 64 * GLDS * 2;
#pragma unroll
            for (int q = 0; q < 2; q++) {
                int k = (laseg + q) * 8;
                cp16(sa + (uint32_t)(larow * GLDS + k) * 2, ap + k, k0 + k + 8 <= K);
            }
            {
                int k = lbseg * 8;
                cp16(sb + (uint32_t)(lbrow * GLDS + k) * 2, bp + k, brow && (k0 + k + 8 <= K));
            }
            cp_commit();
            cp_wait1();
        } else {
            cp_wait0();
        }
        __syncthreads();

        int s = ch & 1;
        uint32_t sa = sa0 + s * 128 * GLDS * 2;
        uint32_t sb = sb0 + s * 64 * GLDS * 2;

        uint32_t afr[2][2][4], bfr[2][2][4];
#pragma unroll
        for (int ks = 0; ks < 2; ks++) {
#pragma unroll
            for (int wm = 0; wm < 2; wm++) {
                int r = wm_ * 32 + wm * 16 + (lane & 15);
                int cc = ks * 16 + ((lane >> 4) << 3);
                ldm_x4(afr[ks][wm], sa + (uint32_t)(r * GLDS + cc) * 2);
            }
#pragma unroll
            for (int wn2 = 0; wn2 < 2; wn2++) {
                int n = wn_ * 32 + wn2 * 16 + ((lane >> 4) << 3) + (lane & 7);
                int cc = ks * 16 + (((lane >> 3) & 1) << 3);
                ldm_x4(bfr[ks][wn2], sb + (uint32_t)(n * GLDS + cc) * 2);
            }
        }
#pragma unroll
        for (int ks = 0; ks < 2; ks++)
#pragma unroll
            for (int wm = 0; wm < 2; wm++)
#pragma unroll
                for (int wn = 0; wn < 4; wn++)
                    mma_bf16(acc[wm][wn], afr[ks][wm],
                             bfr[ks][wn >> 1][(wn & 1) * 2],
                             bfr[ks][wn >> 1][(wn & 1) * 2 + 1]);
        __syncthreads();
    }

#pragma unroll
    for (int wm = 0; wm < 2; wm++) {
        int rA = row0 + wm_ * 32 + wm * 16 + (lane >> 2);
#pragma unroll
        for (int wn = 0; wn < 4; wn++) {
            int cB = col0 + wn_ * 32 + wn * 8 + (lane & 3) * 2;
#pragma unroll
            for (int q = 0; q < 4; q++) {
                int r = rA + (q >> 1) * 8;
                int c = cB + (q & 1);
                float v = acc[wm][wn][q];
                if (doRelu) v = fmaxf(v, 0.f);
                if (C && c < N) {
                    if (doRes) v += Res[(size_t)r * ldr + c];
                    C[(size_t)r * ldc + c] = v;
                }
                if (Cb && c < ldcb)
                    Cb[(size_t)r * ldcb + c] = __float2bfloat16(v);
            }
        }
    }
}

// ---------------- hgemm BN=128 (GEMM4 only: grid >= 2/SM) ----------------------
__global__ __launch_bounds__(256)
void hgemm128(const __nv_bfloat16* __restrict__ A, int lda,
              const __nv_bfloat16* __restrict__ Bt, int ldb,
              const float* __restrict__ Res, int ldr,
              float* __restrict__ C, int ldc,
              __nv_bfloat16* __restrict__ Cb, int ldcb,
              int M, int N, int K, int doRelu, int doRes)
{
    __shared__ __nv_bfloat16 sA[2][128 * GLDS];
    __shared__ __nv_bfloat16 sB[2][128 * GLDS];

    int tid = threadIdx.x, lane = tid & 31, wid = tid >> 5;
    int wm_ = wid & 3;
    int wn_ = wid >> 2;
    int row0 = blockIdx.y * 128, col0 = blockIdx.x * 128;
    int nch = (K + 31) / 32;

    float acc[2][8][4];
#pragma unroll
    for (int i = 0; i < 2; i++)
#pragma unroll
        for (int j = 0; j < 8; j++)
#pragma unroll
            for (int q = 0; q < 4; q++) acc[i][j][q] = 0.f;

    uint32_t sa0 = smem_u32(&sA[0][0]);
    uint32_t sb0 = smem_u32(&sB[0][0]);

    int lrow = tid >> 1;
    int lseg = (tid & 1) * 2;

    {
        const __nv_bfloat16* ap = A + (size_t)(row0 + lrow) * lda;
        const __nv_bfloat16* bp = Bt + (size_t)(col0 + lrow) * ldb;
        bool brow = (col0 + lrow) < N;
#pragma unroll
        for (int q = 0; q < 2; q++) {
            int k = (lseg + q) * 8;
            uint32_t off = (uint32_t)(lrow * GLDS + (lseg + q) * 8) * 2;
            cp16(sa0 + off, ap + k, k + 8 <= K);
            cp16(sb0 + off, bp + k, brow && (k + 8 <= K));
        }
    }
    cp_commit();

    for (int ch = 0; ch < nch; ch++) {
        if (ch + 1 < nch) {
            int s = (ch + 1) & 1;
            int k0 = (ch + 1) * 32;
            const __nv_bfloat16* ap = A + (size_t)(row0 + lrow) * lda + k0;
            const __nv_bfloat16* bp = Bt + (size_t)(col0 + lrow) * ldb + k0;
            bool brow = (col0 + lrow) < N;
            uint32_t sa = sa0 + s * 128 * GLDS * 2;
            uint32_t sb = sb0 + s * 128 * GLDS * 2;
#pragma unroll
            for (int q = 0; q < 2; q++) {
                int k = (lseg + q) * 8;
                uint32_t off = (uint32_t)(lrow * GLDS + (lseg + q) * 8) * 2;
                cp16(sa + off, ap + k, k0 + k + 8 <= K);
                cp16(sb + off, bp + k, brow && (k0 + k + 8 <= K));
            }
            cp_commit();
            cp_wait1();
        } else {
            cp_wait0();
        }
        __syncthreads();

        int s = ch & 1;
        uint32_t sa = sa0 + s * 128 * GLDS * 2;
        uint32_t sb = sb0 + s * 128 * GLDS * 2;

#pragma unroll
        for (int ks = 0; ks < 2; ks++) {
            uint32_t afr[2][4], bfr[4][4];
#pragma unroll
            for (int wm = 0; wm < 2; wm++) {
                int r = wm_ * 32 + wm * 16 + (lane & 15);
                int cc = ks * 16 + ((lane >> 4) << 3);
                ldm_x4(afr[wm], sa + (uint32_t)(r * GLDS + cc) * 2);
            }
#pragma unroll
            for (int wn2 = 0; wn2 < 4; wn2++) {
                int n = wn_ * 64 + wn2 * 16 + ((lane >> 4) << 3) + (lane & 7);
                int cc = ks * 16 + (((lane >> 3) & 1) << 3);
                ldm_x4(bfr[wn2], sb + (uint32_t)(n * GLDS + cc) * 2);
            }
#pragma unroll
            for (int wm = 0; wm < 2; wm++)
#pragma unroll
                for (int wn = 0; wn < 8; wn++)
                    mma_bf16(acc[wm][wn], afr[wm],
                             bfr[wn >> 1][(wn & 1) * 2], bfr[wn >> 1][(wn & 1) * 2 + 1]);
        }
        __syncthreads();
    }

#pragma unroll
    for (int wm = 0; wm < 2; wm++) {
        int rA = row0 + wm_ * 32 + wm * 16 + (lane >> 2);
#pragma unroll
        for (int wn = 0; wn < 8; wn++) {
            int cB = col0 + wn_ * 64 + wn * 8 + (lane & 3) * 2;
#pragma unroll
            for (int q = 0; q < 4; q++) {
                int r = rA + (q >> 1) * 8;
                int c = cB + (q & 1);
                float v = acc[wm][wn][q];
                if (doRelu) v = fmaxf(v, 0.f);
                if (C && c < N) {
                    if (doRes) v += Res[(size_t)r * ldr + c];
                    C[(size_t)r * ldc + c] = v;
                }
                if (Cb && c < ldcb)
                    Cb[(size_t)r * ldcb + c] = __float2bfloat16(v);
            }
        }
    }
}

// ---------------- fp32 -> bf16 copy ------------------------------------------
__global__ void f2b_ker(const float* __restrict__ x, __nv_bfloat16* __restrict__ y, int n)
{
    int i = (blockIdx.x * blockDim.x + threadIdx.x) * 4;
    if (i + 3 < n) {
        float4 v = *(const float4*)(x + i);
        *(__nv_bfloat162*)(y + i)     = __floats2bfloat162_rn(v.x, v.y);
        *(__nv_bfloat162*)(y + i + 2) = __floats2bfloat162_rn(v.z, v.w);
    }
}

// ---------------- weight transpose + convert ---------------------------------
__global__ void wtrans_ker(const float* __restrict__ W, __nv_bfloat16* __restrict__ Wt,
                           int K, int N, int ldt)
{
    __shared__ float t[32][33];
    int kb = blockIdx.y * 32, nb = blockIdx.x * 32;
    int tx = threadIdx.x, ty = threadIdx.y;
#pragma unroll
    for (int i = ty; i < 32; i += 8) {
        int k = kb + i, n = nb + tx;
        t[i][tx] = (k < K && n < N) ? W[(size_t)k * N + n] : 0.f;
    }
    __syncthreads();
#pragma unroll
    for (int i = ty; i < 32; i += 8) {
        int n = nb + i, k = kb + tx;
        if (n < N && k < ldt)
            Wt[(size_t)n * ldt + k] = __float2bfloat16(t[tx][i]);
    }
}

// ---------------- batched cosine similarity (symmetric, fused norms) ---------
__device__ const int g_ntt[10] = {0, 0, 0, 0, 1, 1, 1, 2, 2, 3};
__device__ const int g_mtt[10] = {0, 1, 2, 3, 1, 2, 3, 2, 3, 3};

__global__ __launch_bounds__(256)
void sim_ker(const float* __restrict__ u1, float* __restrict__ sim)
{
    __shared__ float An[32][33];
    __shared__ float Am[32][33];
    __shared__ float nn_s[32], nm_s[32];
    int b = blockIdx.z;
    int nt = g_ntt[blockIdx.x], mt = g_mtt[blockIdx.x];
    int tid = threadIdx.x;
    int tx = tid & 15, ty = tid >> 4;
    const float* base = u1 + (size_t)b * NN * D4;

    float acc[2][2] = {{0.f, 0.f}, {0.f, 0.f}};
    float sq_n = 0.f, sq_m = 0.f;
    int lr = tid >> 3;
    int lc = (tid & 7) * 4;
    for (int k0 = 0; k0 < D4; k0 += 32) {
#pragma unroll
        for (int i = 0; i < 4; i++) {
            int k = k0 + lc + i;
            float vn = (k < D4) ? base[(size_t)(nt * 32 + lr) * D4 + k] : 0.f;
            float vm = (k < D4) ? base[(size_t)(mt * 32 + lr) * D4 + k] : 0.f;
            An[lr][lc + i] = vn;
            Am[lr][lc + i] = vm;
            sq_n += vn * vn;
            sq_m += vm * vm;
        }
        __syncthreads();
#pragma unroll
        for (int k = 0; k < 32; k++) {
            float a0 = An[ty * 2][k], a1 = An[ty * 2 + 1][k];
            float b0 = Am[tx * 2][k], b1 = Am[tx * 2 + 1][k];
            acc[0][0] += a0 * b0; acc[0][1] += a0 * b1;
            acc[1][0] += a1 * b0; acc[1][1] += a1 * b1;
        }
        __syncthreads();
    }

    // reduce per-row sum-of-squares (8 partials per row) and form inv norms
    An[lr][lc >> 2] = sq_n;
    Am[lr][lc >> 2] = sq_m;
    __syncthreads();
    if (tid < 32) {
        float s = 0.f;
#pragma unroll
        for (int e = 0; e < 8; e++) s += An[tid][e];
        nn_s[tid] = rsqrtf(s);
    } else if (tid < 64) {
        int r = tid - 32;
        float s = 0.f;
#pragma unroll
        for (int e = 0; e < 8; e++) s += Am[r][e];
        nm_s[r] = rsqrtf(s);
    }
    __syncthreads();

    bool mirror = (nt != mt);
#pragma unroll
    for (int i = 0; i < 2; i++)
#pragma unroll
        for (int j = 0; j < 2; j++) {
            int nr = ty * 2 + i;
            int mr = tx * 2 + j;
            int n = nt * 32 + nr;
            int m = mt * 32 + mr;
            float v = acc[i][j] * nn_s[nr] * nm_s[mr];
            v = fminf(1.f, fmaxf(-1.f, v));
            sim[((size_t)b * NN + n) * NN + m] = v;
            if (mirror)
                sim[((size_t)b * NN + m) * NN + n] = v;
        }
}

// ---------------- top-2 neighbors (warp per row) ------------------------------
__global__ __launch_bounds__(256)
void top2_ker(const float* __restrict__ sim, int* __restrict__ idx)
{
    int row  = (blockIdx.x * blockDim.x + threadIdx.x) >> 5;
    int lane = threadIdx.x & 31;
    if (row >= MT) return;
    const float* p = sim + (size_t)row * NN;

    float b0 = -1e30f, b1 = -1e30f;
    int i0 = NN, i1 = NN;
#pragma unroll
    for (int e = 0; e < 4; e++) {
        int m = lane + e * 32;
        float v = p[m];
        if (v > b0 || (v == b0 && m < i0)) { b1 = b0; i1 = i0; b0 = v; i0 = m; }
        else if (v > b1 || (v == b1 && m < i1)) { b1 = v; i1 = m; }
    }
#pragma unroll
    for (int o = 16; o; o >>= 1) {
        float c0 = __shfl_down_sync(0xffffffffu, b0, o);
        int   j0 = __shfl_down_sync(0xffffffffu, i0, o);
        float c1 = __shfl_down_sync(0xffffffffu, b1, o);
        int   j1 = __shfl_down_sync(0xffffffffu, i1, o);
        bool firstMine = (b0 > c0) || (b0 == c0 && i0 < j0);
        if (firstMine) {
            if (c0 > b1 || (c0 == b1 && j0 < i1)) { b1 = c0; i1 = j0; }
        } else {
            float nb1; int ni1;
            if (b0 > c1 || (b0 == c1 && i0 < j1)) { nb1 = b0; ni1 = i0; }
            else                                   { nb1 = c1; ni1 = j1; }
            b0 = c0; i0 = j0; b1 = nb1; i1 = ni1;
        }
    }
    if (lane == 0) { idx[row * 2 + 0] = i0; idx[row * 2 + 1] = i1; }
}

// ---------------- argmax over 151 classes (warp per row) ----------------------
__global__ __launch_bounds__(256)
void argmax_ker(const float* __restrict__ dists, int* __restrict__ preds)
{
    int row  = (blockIdx.x * blockDim.x + threadIdx.x) >> 5;
    int lane = threadIdx.x & 31;
    if (row >= MT) return;
    const float* p = dists + (size_t)row * NC;

    float bv = -1e30f; int bi = NC;
#pragma unroll
    for (int e = 0; e < 5; e++) {
        int c = lane + e * 32;
        if (c < NC) {
            float v = p[c];
            if (v > bv || (v == bv && c < bi)) { bv = v; bi = c; }
        }
    }
#pragma unroll
    for (int o = 16; o; o >>= 1) {
        float cv = __shfl_down_sync(0xffffffffu, bv, o);
        int   ci = __shfl_down_sync(0xffffffffu, bi, o);
        if (cv > bv || (cv == bv && ci < bi)) { bv = cv; bi = ci; }
    }
    if (lane == 0) preds[row] = bi;
}

// ---------------- conv1: 32x16 output tile, 2 pixels/thread ------------------
#define C1W 34    // in_s row width (32 + 2 halo)
__global__ __launch_bounds__(256)
void conv1_ker(const float* __restrict__ freq, const float* __restrict__ sim,
               const int* __restrict__ preds, const float* __restrict__ w1,
               float* __restrict__ h1)
{
    extern __shared__ float sm[];
    float* in_s = sm;                  // [52][18][34] = 31824 floats
    float* w_s  = sm + 52 * 18 * C1W;  // [52][10][12] = 6240 floats
    int b = blockIdx.z, tyb = blockIdx.y, txb = blockIdx.x;
    int tid = threadIdx.x;

    for (int idx = tid; idx < 520; idx += 256) {
        int c = idx / 10, o = idx % 10;
        const float* src = w1 + (o * 52 + c) * 9;
        float* dst = w_s + (size_t)idx * 12;
#pragma unroll
        for (int k = 0; k < 9; k++) dst[k] = src[k];
        dst[9] = 0.f; dst[10] = 0.f; dst[11] = 0.f;
    }

    int y0 = tyb * 16 - 1, x0 = txb * 32 - 1;
    const int* pb = preds + b * NN;
    for (int p = tid; p < 18 * C1W; p += 256) {
        int yy = p / C1W, xx = p % C1W;
        int y = y0 + yy, x = x0 + xx;
        if ((unsigned)y < (unsigned)NN && (unsigned)x < (unsigned)NN) {
            int pair = pb[y] * NC + pb[x];
            const float* fr = freq + (size_t)pair * NP;
#pragma unroll 1
            for (int c = 0; c < NP; c++) in_s[c * 18 * C1W + p] = fr[c];
            in_s[NP * 18 * C1W + p] = sim[((size_t)b * NN + y) * NN + x];
        } else {
#pragma unroll 1
            for (int c = 0; c < 52; c++) in_s[c * 18 * C1W + p] = 0.f;
        }
    }
    __syncthreads();

    int tyy = tid >> 4, txx = tid & 15;   // 16x16 threads; pixels txx and txx+16
    float acc0[10], acc1[10];
#pragma unroll
    for (int o = 0; o < 10; o++) { acc0[o] = 0.f; acc1[o] = 0.f; }

    for (int c = 0; c < 52; c++) {
        float v0[9], v1[9];
#pragma unroll
        for (int dy = 0; dy < 3; dy++)
#pragma unroll
            for (int dx = 0; dx < 3; dx++) {
                int base = c * 18 * C1W + (tyy + dy) * C1W + dx;
                v0[dy * 3 + dx] = in_s[base + txx];
                v1[dy * 3 + dx] = in_s[base + txx + 16];
            }
        const float4* wv = (const float4*)(w_s + (size_t)(c * 10) * 12);
#pragma unroll
        for (int o = 0; o < 10; o++) {
            float4 w0 = wv[o * 3 + 0];
            float4 w4 = wv[o * 3 + 1];
            float  w8 = ((const float*)wv)[o * 12 + 8];
            acc0[o] += w0.x * v0[0] + w0.y * v0[1] + w0.z * v0[2] + w0.w * v0[3]
                     + w4.x * v0[4] + w4.y * v0[5] + w4.z * v0[6] + w4.w * v0[7]
                     + w8 * v0[8];
            acc1[o] += w0.x * v1[0] + w0.y * v1[1] + w0.z * v1[2] + w0.w * v1[3]
                     + w4.x * v1[4] + w4.y * v1[5] + w4.z * v1[6] + w4.w * v1[7]
                     + w8 * v1[8];
        }
    }
    int y = tyb * 16 + tyy;
    int x0o = txb * 32 + txx;
#pragma unroll
    for (int o = 0; o < 10; o++) {
        size_t rowbase = (((size_t)b * 10 + o) * NN + y) * NN;
        h1[rowbase + x0o]      = acc0[o];
        h1[rowbase + x0o + 16] = acc1[o];
    }
}

// ---------------- conv2 (+ conv3 folded) + tanh ------------------------------
__global__ __launch_bounds__(256)
void conv23_ker(const float* __restrict__ h1, const float* __restrict__ w2,
                const float* __restrict__ w3, float* __restrict__ adj)
{
    __shared__ float in_s[10][18][18];
    __shared__ float we[10][9];
    int b = blockIdx.z, tyb = blockIdx.y, txb = blockIdx.x;
    int tid = threadIdx.x;

    if (tid < 90) {
        int c = tid / 9, k = tid % 9;
        float s = 0.f;
#pragma unroll
        for (int o = 0; o < 5; o++) s += w3[o] * w2[(o * 10 + c) * 9 + k];
        we[c][k] = s;
    }
    int y0 = tyb * 16 - 1, x0 = txb * 16 - 1;
    for (int p = tid; p < 324; p += 256) {
        int yy = p / 18, xx = p % 18;
        int y = y0 + yy, x = x0 + xx;
        bool ok = ((unsigned)y < (unsigned)NN) && ((unsigned)x < (unsigned)NN);
#pragma unroll
        for (int c = 0; c < 10; c++)
            in_s[c][yy][xx] = ok ? h1[(((size_t)b * 10 + c) * NN + y) * NN + x] : 0.f;
    }
    __syncthreads();

    int tyy = tid >> 4, txx = tid & 15;
    float acc = 0.f;
#pragma unroll
    for (int c = 0; c < 10; c++)
#pragma unroll
        for (int dy = 0; dy < 3; dy++)
#pragma unroll
            for (int dx = 0; dx < 3; dx++)
                acc += we[c][dy * 3 + dx] * in_s[c][tyy + dy][txx + dx];
    adj[((size_t)b * NN + tyb * 16 + tyy) * NN + txb * 16 + txx] = tanhf(acc);
}

// ---- aggregation w/ fused gather, 64x64 tile, 4x4 acc/thread ----------------
#define ALD 65
#define GLD2 68
__global__ __launch_bounds__(256)
void agg_ker(const float* __restrict__ adj, const float* __restrict__ u1,
             const int* __restrict__ idx, __nv_bfloat16* __restrict__ oflb)
{
    __shared__ float As[32][ALD];
    __shared__ float Gs[32][GLD2];
    int b = blockIdx.z, nt = blockIdx.y, kt = blockIdx.x;
    int tid = threadIdx.x;
    int tx = tid & 15, ty = tid >> 4;
    int n0 = nt * 64, k0 = kt * 64;
    const float* adjb = adj + (size_t)b * NN * NN;
    const float* u1b  = u1 + (size_t)b * NN * D4;
    const int*   idxb = idx + b * NN * 2;

    float acc[4][4];
#pragma unroll
    for (int i = 0; i < 4; i++)
#pragma unroll
        for (int j = 0; j < 4; j++) acc[i][j] = 0.f;

    int am  = tid & 31;
    int anb = (tid >> 5) * 8;
    int gm  = tid >> 3;
    int gk  = (tid & 7) * 8;

    for (int m0 = 0; m0 < NN; m0 += 32) {
#pragma unroll
        for (int e = 0; e < 8; e++) {
            int n = anb + e;
            As[am][n] = adjb[(size_t)(n0 + n) * NN + m0 + am];
        }
        int s0 = idxb[(m0 + gm) * 2 + 0];
        int s1 = idxb[(m0 + gm) * 2 + 1];
#pragma unroll
        for (int e = 0; e < 8; e++) {
            int k = k0 + gk + e;
            float v = 0.f;
            if (k < D2) {
                int half = (k >= D4);
                v = u1b[(size_t)(half ? s1 : s0) * D4 + (k - (half ? D4 : 0))];
            }
            Gs[gm][gk + e] = v;
        }
        __syncthreads();
#pragma unroll
        for (int m = 0; m < 32; m++) {
            float a[4], g[4];
#pragma unroll
            for (int i = 0; i < 4; i++) a[i] = As[m][ty * 4 + i];
#pragma unroll
            for (int j = 0; j < 4; j++) g[j] = Gs[m][tx * 4 + j];
#pragma unroll
            for (int i = 0; i < 4; i++)
#pragma unroll
                for (int j = 0; j < 4; j++)
                    acc[i][j] += a[i] * g[j];
        }
        __syncthreads();
    }
#pragma unroll
    for (int i = 0; i < 4; i++) {
        int n = n0 + ty * 4 + i;
#pragma unroll
        for (int j = 0; j < 4; j++) {
            int k = k0 + tx * 4 + j;
            if (k < D2P)
                oflb[((size_t)b * NN + n) * D2P + k] = __float2bfloat16(acc[i][j]);
        }
    }
}

// ---------------- launcher ----------------------------------------------------
extern "C" void kernel_launch(void* const* d_in, const int* in_sizes, int n_in,
                              void* d_out, int out_size)
{
    const float* feat  = (const float*)d_in[0];
    const float* dists = (const float*)d_in[1];
    const float* Wc    = (const float*)d_in[2];
    const float* Wu    = (const float*)d_in[3];
    const float* Wo    = (const float*)d_in[4];
    const float* Wd    = (const float*)d_in[5];
    const float* c1    = (const float*)d_in[6];
    const float* c2    = (const float*)d_in[7];
    const float* c3    = (const float*)d_in[8];
    const float* ft    = (const float*)d_in[9];
    float* out = (float*)d_out;

    __nv_bfloat16 *featb, *compb, *oflb, *umb, *WcT, *WuT, *WoT, *WdT;
    float *u1, *sim, *h1, *adj;
    int *idx, *preds;
    cudaGetSymbolAddress((void**)&featb, g_featb);
    cudaGetSymbolAddress((void**)&compb, g_compb);
    cudaGetSymbolAddress((void**)&u1,    g_u1);
    cudaGetSymbolAddress((void**)&oflb,  g_oflb);
    cudaGetSymbolAddress((void**)&umb,   g_umb);
    cudaGetSymbolAddress((void**)&WcT,   g_WcT);
    cudaGetSymbolAddress((void**)&WuT,   g_WuT);
    cudaGetSymbolAddress((void**)&WoT,   g_WoT);
    cudaGetSymbolAddress((void**)&WdT,   g_WdT);
    cudaGetSymbolAddress((void**)&sim,   g_sim);
    cudaGetSymbolAddress((void**)&idx,   g_idx);
    cudaGetSymbolAddress((void**)&preds, g_preds);
    cudaGetSymbolAddress((void**)&h1,    g_h1);
    cudaGetSymbolAddress((void**)&adj,   g_adj);

    const int conv1_smem = (52 * 18 * C1W + 52 * 10 * 12) * 4;   // 152256 B
    cudaFuncSetAttribute(conv1_ker, cudaFuncAttributeMaxDynamicSharedMemorySize, conv1_smem);

    dim3 tb(32, 8);

    // Launch order: hgemm1 at 0-based launch #3 (the one ncu captures).
    f2b_ker<<<(MT * DD / 4 + 255) / 256, 256>>>(feat, featb, MT * DD);          // 0
    wtrans_ker<<<dim3((D4 + 31) / 32, (DD + 31) / 32),  tb>>>(Wc, WcT, DD, D4, DD);  // 1
    argmax_ker<<<MT * 32 / 256, 256>>>(dists, preds);                            // 2
    // 3. compb = bf16(relu(feat @ Wc))   <- PROFILED
    hgemm<<<dim3(18, 16), 256>>>(featb, DD, WcT, DD,
        nullptr, 0, nullptr, 0, compb, D4P, MT, D4, DD, 1, 0);
    wtrans_ker<<<dim3((D4 + 31) / 32, (D4P + 31) / 32), tb>>>(Wu, WuT, D4, D4, D4P); // 4
    // 5. u1 = relu(comp @ Wu)
    hgemm<<<dim3(18, 16), 256>>>(compb, D4P, WuT, D4P,
        nullptr, 0, u1, D4, nullptr, 0, MT, D4, D4P, 1, 0);
    wtrans_ker<<<dim3((D4 + 31) / 32, (D2P + 31) / 32), tb>>>(Wo, WoT, D2, D4, D2P); // 6
    wtrans_ker<<<dim3((DD + 31) / 32, (D4P + 31) / 32), tb>>>(Wd, WdT, D4, DD, D4P); // 7
    // 8. sim (symmetric, norms fused)
    sim_ker<<<dim3(10, 1, BB), 256>>>(u1, sim);
    // 9. top-2
    top2_ker<<<MT * 32 / 256, 256>>>(sim, idx);
    // 10. conv1 (32x16 tile, 2 px/thread)
    conv1_ker<<<dim3(4, 8, BB), 256, conv1_smem>>>(ft, sim, preds, c1, h1);
    // 11. conv2+conv3+tanh
    conv23_ker<<<dim3(8, 8, BB), 256>>>(h1, c2, c3, adj);
    // 12. oflb = bf16(adj @ gather(u1, idx))
    agg_ker<<<dim3((D2P + 63) / 64, 2, BB), 256>>>(adj, u1, idx, oflb);
    // 13. umb = bf16(relu(ofl @ Wo))
    hgemm<<<dim3(18, 16), 256>>>(oflb, D2P, WoT, D2P,
        nullptr, 0, nullptr, 0, umb, D4P, MT, D4, D2P, 1, 0);
    // 14. out = relu(um @ Wd) + feat
    hgemm128<<<dim3(35, 16), 256>>>(umb, D4P, WdT, D4P,
        feat, DD, out, DD, nullptr, 0, MT, DD, D4P, 1, 1);
}

// round 15
// speedup vs baseline: 1.0303x; 1.0303x over previous
#include <cuda_runtime.h>
#include <cuda_bf16.h>
#include <cstdint>
#include <math.h>

// Problem constants
#define BB   16
#define NN   128
#define DD   4424
#define D4   1106
#define D4P  1112
#define D2   2212
#define D2P  2216
#define NC   151
#define NP   51
#define MT   2048

// ---------------- scratch ------------------------------------------------------
__device__ __nv_bfloat16 g_featb[MT * DD];
__device__ __nv_bfloat16 g_compb[MT * D4P];
__device__ float         g_u1   [MT * D4];
__device__ __nv_bfloat16 g_oflb [MT * D2P];
__device__ __nv_bfloat16 g_umb  [MT * D4P];
__device__ __nv_bfloat16 g_WcT  [(size_t)D4 * DD];
__device__ __nv_bfloat16 g_WuT  [(size_t)D4 * D4P];
__device__ __nv_bfloat16 g_WoT  [(size_t)D4 * D2P];
__device__ __nv_bfloat16 g_WdT  [(size_t)DD * D4P];
__device__ float g_sim  [BB * NN * NN];
__device__ int   g_idx  [BB * NN * 2];
__device__ int   g_preds[MT];
__device__ float g_h1   [BB * 10 * NN * NN];
__device__ float g_adj  [BB * NN * NN];

// ---------------- PTX helpers --------------------------------------------------
__device__ __forceinline__ uint32_t smem_u32(const void* p) {
    uint32_t a;
    asm("{ .reg .u64 t; cvta.to.shared.u64 t, %1; cvt.u32.u64 %0, t; }" : "=r"(a) : "l"(p));
    return a;
}
__device__ __forceinline__ void cp16(uint32_t dst, const void* src, bool valid) {
    int sz = valid ? 16 : 0;
    asm volatile("cp.async.cg.shared.global [%0], [%1], 16, %2;"
                 :: "r"(dst), "l"(src), "r"(sz));
}
__device__ __forceinline__ void cp_commit() {
    asm volatile("cp.async.commit_group;" ::: "memory");
}
__device__ __forceinline__ void cp_wait0() {
    asm volatile("cp.async.wait_group 0;" ::: "memory");
}
__device__ __forceinline__ void cp_wait1() {
    asm volatile("cp.async.wait_group 1;" ::: "memory");
}
__device__ __forceinline__ void ldm_x4(uint32_t* r, uint32_t addr) {
    asm volatile("ldmatrix.sync.aligned.m8n8.x4.shared.b16 {%0,%1,%2,%3}, [%4];"
                 : "=r"(r[0]), "=r"(r[1]), "=r"(r[2]), "=r"(r[3]) : "r"(addr));
}
__device__ __forceinline__ void mma_bf16(float* c, const uint32_t* a,
                                         uint32_t b0, uint32_t b1) {
    asm volatile(
        "mma.sync.aligned.m16n8k16.row.col.f32.bf16.bf16.f32 "
        "{%0,%1,%2,%3}, {%4,%5,%6,%7}, {%8,%9}, {%0,%1,%2,%3};"
        : "+f"(c[0]), "+f"(c[1]), "+f"(c[2]), "+f"(c[3])
        : "r"(a[0]), "r"(a[1]), "r"(a[2]), "r"(a[3]), "r"(b0), "r"(b1));
}

#define GLDS 40

// ---------------- hgemm BN=64 (proven config) ----------------------------------
__global__ __launch_bounds__(256)
void hgemm(const __nv_bfloat16* __restrict__ A, int lda,
           const __nv_bfloat16* __restrict__ Bt, int ldb,
           const float* __restrict__ Res, int ldr,
           float* __restrict__ C, int ldc,
           __nv_bfloat16* __restrict__ Cb, int ldcb,
           int M, int N, int K, int doRelu, int doRes)
{
    __shared__ __nv_bfloat16 sA[2][128 * GLDS];
    __shared__ __nv_bfloat16 sB[2][64 * GLDS];

    int tid = threadIdx.x, lane = tid & 31, wid = tid >> 5;
    int wm_ = wid & 3;
    int wn_ = wid >> 2;
    int row0 = blockIdx.y * 128, col0 = blockIdx.x * 64;
    int nch = (K + 31) / 32;

    float acc[2][4][4];
#pragma unroll
    for (int i = 0; i < 2; i++)
#pragma unroll
        for (int j = 0; j < 4; j++)
#pragma unroll
            for (int q = 0; q < 4; q++) acc[i][j][q] = 0.f;

    uint32_t sa0 = smem_u32(&sA[0][0]);
    uint32_t sb0 = smem_u32(&sB[0][0]);

    int larow = tid >> 1;
    int laseg = (tid & 1) * 2;
    int lbrow = tid >> 2;
    int lbseg = tid & 3;

    {
        const __nv_bfloat16* ap = A + (size_t)(row0 + larow) * lda;
        const __nv_bfloat16* bp = Bt + (size_t)(col0 + lbrow) * ldb;
        bool brow = (col0 + lbrow) < N;
#pragma unroll
        for (int q = 0; q < 2; q++) {
            int k = (laseg + q) * 8;
            cp16(sa0 + (uint32_t)(larow * GLDS + k) * 2, ap + k, k + 8 <= K);
        }
        {
            int k = lbseg * 8;
            cp16(sb0 + (uint32_t)(lbrow * GLDS + k) * 2, bp + k, brow && (k + 8 <= K));
        }
    }
    cp_commit();

    for (int ch = 0; ch < nch; ch++) {
        if (ch + 1 < nch) {
            int s = (ch + 1) & 1;
            int k0 = (ch + 1) * 32;
            const __nv_bfloat16* ap = A + (size_t)(row0 + larow) * lda + k0;
            const __nv_bfloat16* bp = Bt + (size_t)(col0 + lbrow) * ldb + k0;
            bool brow = (col0 + lbrow) < N;
            uint32_t sa = sa0 + s * 128 * GLDS * 2;
            uint32_t sb = sb0 + s * 64 * GLDS * 2;
#pragma unroll
            for (int q = 0; q < 2; q++) {
                int k = (laseg + q) * 8;
                cp16(sa + (uint32_t)(larow * GLDS + k) * 2, ap + k, k0 + k + 8 <= K);
            }
            {
                int k = lbseg * 8;
                cp16(sb + (uint32_t)(lbrow * GLDS + k) * 2, bp + k, brow && (k0 + k + 8 <= K));
            }
            cp_commit();
            cp_wait1();
        } else {
            cp_wait0();
        }
        __syncthreads();

        int s = ch & 1;
        uint32_t sa = sa0 + s * 128 * GLDS * 2;
        uint32_t sb = sb0 + s * 64 * GLDS * 2;

        uint32_t afr[2][2][4], bfr[2][2][4];
#pragma unroll
        for (int ks = 0; ks < 2; ks++) {
#pragma unroll
            for (int wm = 0; wm < 2; wm++) {
                int r = wm_ * 32 + wm * 16 + (lane & 15);
                int cc = ks * 16 + ((lane >> 4) << 3);
                ldm_x4(afr[ks][wm], sa + (uint32_t)(r * GLDS + cc) * 2);
            }
#pragma unroll
            for (int wn2 = 0; wn2 < 2; wn2++) {
                int n = wn_ * 32 + wn2 * 16 + ((lane >> 4) << 3) + (lane & 7);
                int cc = ks * 16 + (((lane >> 3) & 1) << 3);
                ldm_x4(bfr[ks][wn2], sb + (uint32_t)(n * GLDS + cc) * 2);
            }
        }
#pragma unroll
        for (int ks = 0; ks < 2; ks++)
#pragma unroll
            for (int wm = 0; wm < 2; wm++)
#pragma unroll
                for (int wn = 0; wn < 4; wn++)
                    mma_bf16(acc[wm][wn], afr[ks][wm],
                             bfr[ks][wn >> 1][(wn & 1) * 2],
                             bfr[ks][wn >> 1][(wn & 1) * 2 + 1]);
        __syncthreads();
    }

#pragma unroll
    for (int wm = 0; wm < 2; wm++) {
        int rA = row0 + wm_ * 32 + wm * 16 + (lane >> 2);
#pragma unroll
        for (int wn = 0; wn < 4; wn++) {
            int cB = col0 + wn_ * 32 + wn * 8 + (lane & 3) * 2;
#pragma unroll
            for (int q = 0; q < 4; q++) {
                int r = rA + (q >> 1) * 8;
                int c = cB + (q & 1);
                float v = acc[wm][wn][q];
                if (doRelu) v = fmaxf(v, 0.f);
                if (C && c < N) {
                    if (doRes) v += Res[(size_t)r * ldr + c];
                    C[(size_t)r * ldc + c] = v;
                }
                if (Cb && c < ldcb)
                    Cb[(size_t)r * ldcb + c] = __float2bfloat16(v);
            }
        }
    }
}

// ---------------- hgemm BN=128 (GEMM4 only) ------------------------------------
__global__ __launch_bounds__(256)
void hgemm128(const __nv_bfloat16* __restrict__ A, int lda,
              const __nv_bfloat16* __restrict__ Bt, int ldb,
              const float* __restrict__ Res, int ldr,
              float* __restrict__ C, int ldc,
              __nv_bfloat16* __restrict__ Cb, int ldcb,
              int M, int N, int K, int doRelu, int doRes)
{
    __shared__ __nv_bfloat16 sA[2][128 * GLDS];
    __shared__ __nv_bfloat16 sB[2][128 * GLDS];

    int tid = threadIdx.x, lane = tid & 31, wid = tid >> 5;
    int wm_ = wid & 3;
    int wn_ = wid >> 2;
    int row0 = blockIdx.y * 128, col0 = blockIdx.x * 128;
    int nch = (K + 31) / 32;

    float acc[2][8][4];
#pragma unroll
    for (int i = 0; i < 2; i++)
#pragma unroll
        for (int j = 0; j < 8; j++)
#pragma unroll
            for (int q = 0; q < 4; q++) acc[i][j][q] = 0.f;

    uint32_t sa0 = smem_u32(&sA[0][0]);
    uint32_t sb0 = smem_u32(&sB[0][0]);

    int lrow = tid >> 1;
    int lseg = (tid & 1) * 2;

    {
        const __nv_bfloat16* ap = A + (size_t)(row0 + lrow) * lda;
        const __nv_bfloat16* bp = Bt + (size_t)(col0 + lrow) * ldb;
        bool brow = (col0 + lrow) < N;
#pragma unroll
        for (int q = 0; q < 2; q++) {
            int k = (lseg + q) * 8;
            uint32_t off = (uint32_t)(lrow * GLDS + (lseg + q) * 8) * 2;
            cp16(sa0 + off, ap + k, k + 8 <= K);
            cp16(sb0 + off, bp + k, brow && (k + 8 <= K));
        }
    }
    cp_commit();

    for (int ch = 0; ch < nch; ch++) {
        if (ch + 1 < nch) {
            int s = (ch + 1) & 1;
            int k0 = (ch + 1) * 32;
            const __nv_bfloat16* ap = A + (size_t)(row0 + lrow) * lda + k0;
            const __nv_bfloat16* bp = Bt + (size_t)(col0 + lrow) * ldb + k0;
            bool brow = (col0 + lrow) < N;
            uint32_t sa = sa0 + s * 128 * GLDS * 2;
            uint32_t sb = sb0 + s * 128 * GLDS * 2;
#pragma unroll
            for (int q = 0; q < 2; q++) {
                int k = (lseg + q) * 8;
                uint32_t off = (uint32_t)(lrow * GLDS + (lseg + q) * 8) * 2;
                cp16(sa + off, ap + k, k0 + k + 8 <= K);
                cp16(sb + off, bp + k, brow && (k0 + k + 8 <= K));
            }
            cp_commit();
            cp_wait1();
        } else {
            cp_wait0();
        }
        __syncthreads();

        int s = ch & 1;
        uint32_t sa = sa0 + s * 128 * GLDS * 2;
        uint32_t sb = sb0 + s * 128 * GLDS * 2;

#pragma unroll
        for (int ks = 0; ks < 2; ks++) {
            uint32_t afr[2][4], bfr[4][4];
#pragma unroll
            for (int wm = 0; wm < 2; wm++) {
                int r = wm_ * 32 + wm * 16 + (lane & 15);
                int cc = ks * 16 + ((lane >> 4) << 3);
                ldm_x4(afr[wm], sa + (uint32_t)(r * GLDS + cc) * 2);
            }
#pragma unroll
            for (int wn2 = 0; wn2 < 4; wn2++) {
                int n = wn_ * 64 + wn2 * 16 + ((lane >> 4) << 3) + (lane & 7);
                int cc = ks * 16 + (((lane >> 3) & 1) << 3);
                ldm_x4(bfr[wn2], sb + (uint32_t)(n * GLDS + cc) * 2);
            }
#pragma unroll
            for (int wm = 0; wm < 2; wm++)
#pragma unroll
                for (int wn = 0; wn < 8; wn++)
                    mma_bf16(acc[wm][wn], afr[wm],
                             bfr[wn >> 1][(wn & 1) * 2], bfr[wn >> 1][(wn & 1) * 2 + 1]);
        }
        __syncthreads();
    }

#pragma unroll
    for (int wm = 0; wm < 2; wm++) {
        int rA = row0 + wm_ * 32 + wm * 16 + (lane >> 2);
#pragma unroll
        for (int wn = 0; wn < 8; wn++) {
            int cB = col0 + wn_ * 64 + wn * 8 + (lane & 3) * 2;
#pragma unroll
            for (int q = 0; q < 4; q++) {
                int r = rA + (q >> 1) * 8;
                int c = cB + (q & 1);
                float v = acc[wm][wn][q];
                if (doRelu) v = fmaxf(v, 0.f);
                if (C && c < N) {
                    if (doRes) v += Res[(size_t)r * ldr + c];
                    C[(size_t)r * ldc + c] = v;
                }
                if (Cb && c < ldcb)
                    Cb[(size_t)r * ldcb + c] = __float2bfloat16(v);
            }
        }
    }
}

// ---------------- fp32 -> bf16 copy ------------------------------------------
__global__ void f2b_ker(const float* __restrict__ x, __nv_bfloat16* __restrict__ y, int n)
{
    int i = (blockIdx.x * blockDim.x + threadIdx.x) * 4;
    if (i + 3 < n) {
        float4 v = *(const float4*)(x + i);
        *(__nv_bfloat162*)(y + i)     = __floats2bfloat162_rn(v.x, v.y);
        *(__nv_bfloat162*)(y + i + 2) = __floats2bfloat162_rn(v.z, v.w);
    }
}

// ---------------- weight transpose + convert ---------------------------------
__global__ void wtrans_ker(const float* __restrict__ W, __nv_bfloat16* __restrict__ Wt,
                           int K, int N, int ldt)
{
    __shared__ float t[32][33];
    int kb = blockIdx.y * 32, nb = blockIdx.x * 32;
    int tx = threadIdx.x, ty = threadIdx.y;
#pragma unroll
    for (int i = ty; i < 32; i += 8) {
        int k = kb + i, n = nb + tx;
        t[i][tx] = (k < K && n < N) ? W[(size_t)k * N + n] : 0.f;
    }
    __syncthreads();
#pragma unroll
    for (int i = ty; i < 32; i += 8) {
        int n = nb + i, k = kb + tx;
        if (n < N && k < ldt)
            Wt[(size_t)n * ldt + k] = __float2bfloat16(t[tx][i]);
    }
}

// ---------------- batched cosine similarity (symmetric, fused norms) ---------
__device__ const int g_ntt[10] = {0, 0, 0, 0, 1, 1, 1, 2, 2, 3};
__device__ const int g_mtt[10] = {0, 1, 2, 3, 1, 2, 3, 2, 3, 3};

__global__ __launch_bounds__(256)
void sim_ker(const float* __restrict__ u1, float* __restrict__ sim)
{
    __shared__ float An[32][33];
    __shared__ float Am[32][33];
    __shared__ float nn_s[32], nm_s[32];
    int b = blockIdx.z;
    int nt = g_ntt[blockIdx.x], mt = g_mtt[blockIdx.x];
    int tid = threadIdx.x;
    int tx = tid & 15, ty = tid >> 4;
    const float* base = u1 + (size_t)b * NN * D4;

    float acc[2][2] = {{0.f, 0.f}, {0.f, 0.f}};
    float sq_n = 0.f, sq_m = 0.f;
    int lr = tid >> 3;
    int lc = (tid & 7) * 4;
    for (int k0 = 0; k0 < D4; k0 += 32) {
#pragma unroll
        for (int i = 0; i < 4; i++) {
            int k = k0 + lc + i;
            float vn = (k < D4) ? base[(size_t)(nt * 32 + lr) * D4 + k] : 0.f;
            float vm = (k < D4) ? base[(size_t)(mt * 32 + lr) * D4 + k] : 0.f;
            An[lr][lc + i] = vn;
            Am[lr][lc + i] = vm;
            sq_n += vn * vn;
            sq_m += vm * vm;
        }
        __syncthreads();
#pragma unroll
        for (int k = 0; k < 32; k++) {
            float a0 = An[ty * 2][k], a1 = An[ty * 2 + 1][k];
            float b0 = Am[tx * 2][k], b1 = Am[tx * 2 + 1][k];
            acc[0][0] += a0 * b0; acc[0][1] += a0 * b1;
            acc[1][0] += a1 * b0; acc[1][1] += a1 * b1;
        }
        __syncthreads();
    }

    // reduce per-row sum-of-squares (8 partials per row) -> inverse norms
    An[lr][lc >> 2] = sq_n;
    Am[lr][lc >> 2] = sq_m;
    __syncthreads();
    if (tid < 32) {
        float s = 0.f;
#pragma unroll
        for (int e = 0; e < 8; e++) s += An[tid][e];
        nn_s[tid] = rsqrtf(s);
    } else if (tid < 64) {
        int r = tid - 32;
        float s = 0.f;
#pragma unroll
        for (int e = 0; e < 8; e++) s += Am[r][e];
        nm_s[r] = rsqrtf(s);
    }
    __syncthreads();

    bool mirror = (nt != mt);
#pragma unroll
    for (int i = 0; i < 2; i++)
#pragma unroll
        for (int j = 0; j < 2; j++) {
            int nr = ty * 2 + i;
            int mr = tx * 2 + j;
            int n = nt * 32 + nr;
            int m = mt * 32 + mr;
            float v = acc[i][j] * nn_s[nr] * nm_s[mr];
            v = fminf(1.f, fmaxf(-1.f, v));
            sim[((size_t)b * NN + n) * NN + m] = v;
            if (mirror)
                sim[((size_t)b * NN + m) * NN + n] = v;
        }
}

// ---------------- top-2 neighbors (warp per row) ------------------------------
__global__ __launch_bounds__(256)
void top2_ker(const float* __restrict__ sim, int* __restrict__ idx)
{
    int row  = (blockIdx.x * blockDim.x + threadIdx.x) >> 5;
    int lane = threadIdx.x & 31;
    if (row >= MT) return;
    const float* p = sim + (size_t)row * NN;

    float b0 = -1e30f, b1 = -1e30f;
    int i0 = NN, i1 = NN;
#pragma unroll
    for (int e = 0; e < 4; e++) {
        int m = lane + e * 32;
        float v = p[m];
        if (v > b0 || (v == b0 && m < i0)) { b1 = b0; i1 = i0; b0 = v; i0 = m; }
        else if (v > b1 || (v == b1 && m < i1)) { b1 = v; i1 = m; }
    }
#pragma unroll
    for (int o = 16; o; o >>= 1) {
        float c0 = __shfl_down_sync(0xffffffffu, b0, o);
        int   j0 = __shfl_down_sync(0xffffffffu, i0, o);
        float c1 = __shfl_down_sync(0xffffffffu, b1, o);
        int   j1 = __shfl_down_sync(0xffffffffu, i1, o);
        bool firstMine = (b0 > c0) || (b0 == c0 && i0 < j0);
        if (firstMine) {
            if (c0 > b1 || (c0 == b1 && j0 < i1)) { b1 = c0; i1 = j0; }
        } else {
            float nb1; int ni1;
            if (b0 > c1 || (b0 == c1 && i0 < j1)) { nb1 = b0; ni1 = i0; }
            else                                   { nb1 = c1; ni1 = j1; }
            b0 = c0; i0 = j0; b1 = nb1; i1 = ni1;
        }
    }
    if (lane == 0) { idx[row * 2 + 0] = i0; idx[row * 2 + 1] = i1; }
}

// ---------------- argmax over 151 classes (warp per row) ----------------------
__global__ __launch_bounds__(256)
void argmax_ker(const float* __restrict__ dists, int* __restrict__ preds)
{
    int row  = (blockIdx.x * blockDim.x + threadIdx.x) >> 5;
    int lane = threadIdx.x & 31;
    if (row >= MT) return;
    const float* p = dists + (size_t)row * NC;

    float bv = -1e30f; int bi = NC;
#pragma unroll
    for (int e = 0; e < 5; e++) {
        int c = lane + e * 32;
        if (c < NC) {
            float v = p[c];
            if (v > bv || (v == bv && c < bi)) { bv = v; bi = c; }
        }
    }
#pragma unroll
    for (int o = 16; o; o >>= 1) {
        float cv = __shfl_down_sync(0xffffffffu, bv, o);
        int   ci = __shfl_down_sync(0xffffffffu, bi, o);
        if (cv > bv || (cv == bv && ci < bi)) { bv = cv; bi = ci; }
    }
    if (lane == 0) preds[row] = bi;
}

// ---------------- conv1 (R13 proven: 16x16 tile, vectorized weights) ----------
__global__ __launch_bounds__(256)
void conv1_ker(const float* __restrict__ freq, const float* __restrict__ sim,
               const int* __restrict__ preds, const float* __restrict__ w1,
               float* __restrict__ h1)
{
    extern __shared__ float sm[];
    float* in_s = sm;               // [52][18][18]
    float* w_s  = sm + 52 * 324;    // [52][10][12]
    int b = blockIdx.z, tyb = blockIdx.y, txb = blockIdx.x;
    int tid = threadIdx.x;

    for (int idx = tid; idx < 520; idx += 256) {
        int c = idx / 10, o = idx % 10;
        const float* src = w1 + (o * 52 + c) * 9;
        float* dst = w_s + (size_t)idx * 12;
#pragma unroll
        for (int k = 0; k < 9; k++) dst[k] = src[k];
        dst[9] = 0.f; dst[10] = 0.f; dst[11] = 0.f;
    }

    int y0 = tyb * 16 - 1, x0 = txb * 16 - 1;
    const int* pb = preds + b * NN;
    for (int p = tid; p < 324; p += 256) {
        int yy = p / 18, xx = p % 18;
        int y = y0 + yy, x = x0 + xx;
        if ((unsigned)y < (unsigned)NN && (unsigned)x < (unsigned)NN) {
            int pair = pb[y] * NC + pb[x];
            const float* fr = freq + (size_t)pair * NP;
#pragma unroll 1
            for (int c = 0; c < NP; c++) in_s[c * 324 + p] = fr[c];
            in_s[NP * 324 + p] = sim[((size_t)b * NN + y) * NN + x];
        } else {
#pragma unroll 1
            for (int c = 0; c < 52; c++) in_s[c * 324 + p] = 0.f;
        }
    }
    __syncthreads();

    int tyy = tid >> 4, txx = tid & 15;
    float acc[10];
#pragma unroll
    for (int o = 0; o < 10; o++) acc[o] = 0.f;

    for (int c = 0; c < 52; c++) {
        float v[9];
#pragma unroll
        for (int dy = 0; dy < 3; dy++)
#pragma unroll
            for (int dx = 0; dx < 3; dx++)
                v[dy * 3 + dx] = in_s[c * 324 + (tyy + dy) * 18 + (txx + dx)];
        const float4* wv = (const float4*)(w_s + (size_t)(c * 10) * 12);
#pragma unroll
        for (int o = 0; o < 10; o++) {
            float4 w0 = wv[o * 3 + 0];
            float4 w4 = wv[o * 3 + 1];
            float  w8 = ((const float*)wv)[o * 12 + 8];
            acc[o] += w0.x * v[0] + w0.y * v[1] + w0.z * v[2] + w0.w * v[3]
                    + w4.x * v[4] + w4.y * v[5] + w4.z * v[6] + w4.w * v[7]
                    + w8 * v[8];
        }
    }
    int y = tyb * 16 + tyy, x = txb * 16 + txx;
#pragma unroll
    for (int o = 0; o < 10; o++)
        h1[(((size_t)b * 10 + o) * NN + y) * NN + x] = acc[o];
}

// ---------------- conv2 (+ conv3 folded) + tanh ------------------------------
__global__ __launch_bounds__(256)
void conv23_ker(const float* __restrict__ h1, const float* __restrict__ w2,
                const float* __restrict__ w3, float* __restrict__ adj)
{
    __shared__ float in_s[10][18][18];
    __shared__ float we[10][9];
    int b = blockIdx.z, tyb = blockIdx.y, txb = blockIdx.x;
    int tid = threadIdx.x;

    if (tid < 90) {
        int c = tid / 9, k = tid % 9;
        float s = 0.f;
#pragma unroll
        for (int o = 0; o < 5; o++) s += w3[o] * w2[(o * 10 + c) * 9 + k];
        we[c][k] = s;
    }
    int y0 = tyb * 16 - 1, x0 = txb * 16 - 1;
    for (int p = tid; p < 324; p += 256) {
        int yy = p / 18, xx = p % 18;
        int y = y0 + yy, x = x0 + xx;
        bool ok = ((unsigned)y < (unsigned)NN) && ((unsigned)x < (unsigned)NN);
#pragma unroll
        for (int c = 0; c < 10; c++)
            in_s[c][yy][xx] = ok ? h1[(((size_t)b * 10 + c) * NN + y) * NN + x] : 0.f;
    }
    __syncthreads();

    int tyy = tid >> 4, txx = tid & 15;
    float acc = 0.f;
#pragma unroll
    for (int c = 0; c < 10; c++)
#pragma unroll
        for (int dy = 0; dy < 3; dy++)
#pragma unroll
            for (int dx = 0; dx < 3; dx++)
                acc += we[c][dy * 3 + dx] * in_s[c][tyy + dy][txx + dx];
    adj[((size_t)b * NN + tyb * 16 + tyy) * NN + txb * 16 + txx] = tanhf(acc);
}

// ---- aggregation w/ fused gather, 64x64 tile, 4x4 acc/thread ----------------
#define ALD 65
#define GLD2 68
__global__ __launch_bounds__(256)
void agg_ker(const float* __restrict__ adj, const float* __restrict__ u1,
             const int* __restrict__ idx, __nv_bfloat16* __restrict__ oflb)
{
    __shared__ float As[32][ALD];
    __shared__ float Gs[32][GLD2];
    int b = blockIdx.z, nt = blockIdx.y, kt = blockIdx.x;
    int tid = threadIdx.x;
    int tx = tid & 15, ty = tid >> 4;
    int n0 = nt * 64, k0 = kt * 64;
    const float* adjb = adj + (size_t)b * NN * NN;
    const float* u1b  = u1 + (size_t)b * NN * D4;
    const int*   idxb = idx + b * NN * 2;

    float acc[4][4];
#pragma unroll
    for (int i = 0; i < 4; i++)
#pragma unroll
        for (int j = 0; j < 4; j++) acc[i][j] = 0.f;

    int am  = tid & 31;
    int anb = (tid >> 5) * 8;
    int gm  = tid >> 3;
    int gk  = (tid & 7) * 8;

    for (int m0 = 0; m0 < NN; m0 += 32) {
#pragma unroll
        for (int e = 0; e < 8; e++) {
            int n = anb + e;
            As[am][n] = adjb[(size_t)(n0 + n) * NN + m0 + am];
        }
        int s0 = idxb[(m0 + gm) * 2 + 0];
        int s1 = idxb[(m0 + gm) * 2 + 1];
#pragma unroll
        for (int e = 0; e < 8; e++) {
            int k = k0 + gk + e;
            float v = 0.f;
            if (k < D2) {
                int half = (k >= D4);
                v = u1b[(size_t)(half ? s1 : s0) * D4 + (k - (half ? D4 : 0))];
            }
            Gs[gm][gk + e] = v;
        }
        __syncthreads();
#pragma unroll
        for (int m = 0; m < 32; m++) {
            float a[4], g[4];
#pragma unroll
            for (int i = 0; i < 4; i++) a[i] = As[m][ty * 4 + i];
#pragma unroll
            for (int j = 0; j < 4; j++) g[j] = Gs[m][tx * 4 + j];
#pragma unroll
            for (int i = 0; i < 4; i++)
#pragma unroll
                for (int j = 0; j < 4; j++)
                    acc[i][j] += a[i] * g[j];
        }
        __syncthreads();
    }
#pragma unroll
    for (int i = 0; i < 4; i++) {
        int n = n0 + ty * 4 + i;
#pragma unroll
        for (int j = 0; j < 4; j++) {
            int k = k0 + tx * 4 + j;
            if (k < D2P)
                oflb[((size_t)b * NN + n) * D2P + k] = __float2bfloat16(acc[i][j]);
        }
    }
}

// ---------------- launcher ----------------------------------------------------
extern "C" void kernel_launch(void* const* d_in, const int* in_sizes, int n_in,
                              void* d_out, int out_size)
{
    const float* feat  = (const float*)d_in[0];
    const float* dists = (const float*)d_in[1];
    const float* Wc    = (const float*)d_in[2];
    const float* Wu    = (const float*)d_in[3];
    const float* Wo    = (const float*)d_in[4];
    const float* Wd    = (const float*)d_in[5];
    const float* c1    = (const float*)d_in[6];
    const float* c2    = (const float*)d_in[7];
    const float* c3    = (const float*)d_in[8];
    const float* ft    = (const float*)d_in[9];
    float* out = (float*)d_out;

    __nv_bfloat16 *featb, *compb, *oflb, *umb, *WcT, *WuT, *WoT, *WdT;
    float *u1, *sim, *h1, *adj;
    int *idx, *preds;
    cudaGetSymbolAddress((void**)&featb, g_featb);
    cudaGetSymbolAddress((void**)&compb, g_compb);
    cudaGetSymbolAddress((void**)&u1,    g_u1);
    cudaGetSymbolAddress((void**)&oflb,  g_oflb);
    cudaGetSymbolAddress((void**)&umb,   g_umb);
    cudaGetSymbolAddress((void**)&WcT,   g_WcT);
    cudaGetSymbolAddress((void**)&WuT,   g_WuT);
    cudaGetSymbolAddress((void**)&WoT,   g_WoT);
    cudaGetSymbolAddress((void**)&WdT,   g_WdT);
    cudaGetSymbolAddress((void**)&sim,   g_sim);
    cudaGetSymbolAddress((void**)&idx,   g_idx);
    cudaGetSymbolAddress((void**)&preds, g_preds);
    cudaGetSymbolAddress((void**)&h1,    g_h1);
    cudaGetSymbolAddress((void**)&adj,   g_adj);

    const int conv1_smem = (52 * 324 + 52 * 10 * 12) * 4;
    cudaFuncSetAttribute(conv1_ker, cudaFuncAttributeMaxDynamicSharedMemorySize, conv1_smem);

    dim3 tb(32, 8);

    // Launch order: hgemm1 at 0-based launch #3 (the one ncu captures).
    f2b_ker<<<(MT * DD / 4 + 255) / 256, 256>>>(feat, featb, MT * DD);          // 0
    wtrans_ker<<<dim3((D4 + 31) / 32, (DD + 31) / 32),  tb>>>(Wc, WcT, DD, D4, DD);  // 1
    argmax_ker<<<MT * 32 / 256, 256>>>(dists, preds);                            // 2
    // 3. compb = bf16(relu(feat @ Wc))   <- PROFILED
    hgemm<<<dim3(18, 16), 256>>>(featb, DD, WcT, DD,
        nullptr, 0, nullptr, 0, compb, D4P, MT, D4, DD, 1, 0);
    wtrans_ker<<<dim3((D4 + 31) / 32, (D4P + 31) / 32), tb>>>(Wu, WuT, D4, D4, D4P); // 4
    // 5. u1 = relu(comp @ Wu)
    hgemm<<<dim3(18, 16), 256>>>(compb, D4P, WuT, D4P,
        nullptr, 0, u1, D4, nullptr, 0, MT, D4, D4P, 1, 0);
    wtrans_ker<<<dim3((D4 + 31) / 32, (D2P + 31) / 32), tb>>>(Wo, WoT, D2, D4, D2P); // 6
    wtrans_ker<<<dim3((DD + 31) / 32, (D4P + 31) / 32), tb>>>(Wd, WdT, D4, DD, D4P); // 7
    // 8. sim (symmetric, norms fused — the ONLY change vs R13)
    sim_ker<<<dim3(10, 1, BB), 256>>>(u1, sim);
    // 9. top-2
    top2_ker<<<MT * 32 / 256, 256>>>(sim, idx);
    // 10. conv1 (R13 proven)
    conv1_ker<<<dim3(8, 8, BB), 256, conv1_smem>>>(ft, sim, preds, c1, h1);
    // 11. conv2+conv3+tanh
    conv23_ker<<<dim3(8, 8, BB), 256>>>(h1, c2, c3, adj);
    // 12. oflb = bf16(adj @ gather(u1, idx))
    agg_ker<<<dim3((D2P + 63) / 64, 2, BB), 256>>>(adj, u1, idx, oflb);
    // 13. umb = bf16(relu(ofl @ Wo))
    hgemm<<<dim3(18, 16), 256>>>(oflb, D2P, WoT, D2P,
        nullptr, 0, nullptr, 0, umb, D4P, MT, D4, D2P, 1, 0);
    // 14. out = relu(um @ Wd) + feat
    hgemm128<<<dim3(35, 16), 256>>>(umb, D4P, WdT, D4P,
        feat, DD, out, DD, nullptr, 0, MT, DD, D4P, 1, 1);
}